// round 1
// baseline (speedup 1.0000x reference)
#include <cuda_runtime.h>
#include <cuda_bf16.h>
#include <cstdint>

// Problem constants
#define BB 32
#define SS 4096
#define HH 1024
#define ROWS (BB * SS)   // 131072

// Scratch (device globals — no allocation allowed)
__device__ float        g_h[ROWS];
__device__ unsigned int g_min[BB];   // order-preserving encoded float
__device__ unsigned int g_max[BB];

// Order-preserving float <-> uint encoding (monotonic under unsigned compare)
__device__ __forceinline__ unsigned int enc_f(float f) {
    unsigned int u = __float_as_uint(f);
    return (u & 0x80000000u) ? ~u : (u | 0x80000000u);
}
__device__ __forceinline__ float dec_f(unsigned int u) {
    u = (u & 0x80000000u) ? (u & 0x7FFFFFFFu) : ~u;
    return __uint_as_float(u);
}

__global__ void init_k() {
    int i = threadIdx.x;
    if (i < BB) {
        g_min[i] = 0xFFFFFFFFu;  // +inf in encoded space (take atomicMin)
        g_max[i] = 0x00000000u;  // -inf in encoded space (take atomicMax)
    }
}

// One warp per (b,s) row: dot(x_row, W) + bias, masked per-batch min/max via RED atomics.
// Block = 256 threads = 8 warps = 8 consecutive rows. 4096 % 8 == 0, so a block
// never spans a batch boundary.
__global__ __launch_bounds__(256) void gemv_k(const float* __restrict__ x,
                                              const int*   __restrict__ mask,
                                              const float* __restrict__ W,
                                              const float* __restrict__ bias)
{
    __shared__ float ws[HH];
    const int tid = threadIdx.x;
    #pragma unroll
    for (int i = tid; i < HH; i += 256) ws[i] = W[i];
    __syncthreads();

    const int warp = tid >> 5;
    const int lane = tid & 31;
    const long long row = (long long)blockIdx.x * 8 + warp;

    const float4* __restrict__ xr = (const float4*)(x + row * HH);
    const float4* __restrict__ wr = (const float4*)ws;

    float acc = 0.0f;
    #pragma unroll
    for (int j = 0; j < 8; ++j) {       // 1024 floats = 256 float4; 8 per lane
        float4 a  = xr[lane + 32 * j];  // coalesced: consecutive lanes, consecutive 16B
        float4 w4 = wr[lane + 32 * j];
        acc += a.x * w4.x + a.y * w4.y + a.z * w4.z + a.w * w4.w;
    }

    #pragma unroll
    for (int o = 16; o; o >>= 1) acc += __shfl_xor_sync(0xFFFFFFFFu, acc, o);

    if (lane == 0) {
        const float h = acc + bias[0];
        g_h[row] = h;
        if (mask[row]) {
            const int b = (int)(row >> 12);  // row / 4096
            const unsigned int e = enc_f(h);
            atomicMin(&g_min[b], e);         // no return use -> REDG
            atomicMax(&g_max[b], e);
        }
    }
}

__global__ __launch_bounds__(256) void final_k(const int* __restrict__ mask,
                                               float* __restrict__ out)
{
    const int i = blockIdx.x * 256 + threadIdx.x;
    const int b = i >> 12;
    const float hmin = dec_f(g_min[b]);
    const float hmax = dec_f(g_max[b]);
    const float inv  = 1.0f / (hmax - hmin);
    const float h    = g_h[i];
    out[i] = mask[i] ? (h - hmin) * inv : 0.0f;
}

extern "C" void kernel_launch(void* const* d_in, const int* in_sizes, int n_in,
                              void* d_out, int out_size)
{
    const float* x    = (const float*)d_in[0];   // [B,S,H] fp32
    const int*   mask = (const int*)  d_in[1];   // [B,S]   (bool -> int32 assumed)
    const float* W    = (const float*)d_in[2];   // [H]
    const float* bias = (const float*)d_in[3];   // [1]
    float*       out  = (float*)d_out;           // [B,S,1] fp32

    init_k<<<1, 32>>>();
    gemv_k<<<ROWS / 8, 256>>>(x, mask, W, bias);
    final_k<<<ROWS / 256, 256>>>(mask, out);
}

// round 2
// speedup vs baseline: 1.4825x; 1.4825x over previous
#include <cuda_runtime.h>
#include <cuda_bf16.h>
#include <cstdint>

// Problem constants
#define BB 32
#define SS 4096
#define HH 1024
#define ROWS (BB * SS)   // 131072

// Scratch (device global — no allocation allowed)
__device__ float g_h[ROWS];

__device__ __forceinline__ float warp_min(float v) {
    #pragma unroll
    for (int o = 16; o; o >>= 1) v = fminf(v, __shfl_xor_sync(0xFFFFFFFFu, v, o));
    return v;
}
__device__ __forceinline__ float warp_max(float v) {
    #pragma unroll
    for (int o = 16; o; o >>= 1) v = fmaxf(v, __shfl_xor_sync(0xFFFFFFFFu, v, o));
    return v;
}

// ---------------------------------------------------------------------------
// Kernel 1: h = x @ W + b.  One warp per 2 rows, 512 threads/block.
// 16 independent LDG.128 in flight per warp; W staged once per block in smem.
// ---------------------------------------------------------------------------
__global__ __launch_bounds__(512) void gemv_k(const float* __restrict__ x,
                                              const float* __restrict__ W,
                                              const float* __restrict__ bias)
{
    __shared__ float ws[HH];
    const int tid = threadIdx.x;
    #pragma unroll
    for (int i = tid; i < HH; i += 512) ws[i] = W[i];
    __syncthreads();

    const int warp = tid >> 5;
    const int lane = tid & 31;
    const long long r0 = ((long long)blockIdx.x * 16 + warp) * 2;

    const float4* __restrict__ x0 = (const float4*)(x + r0 * HH);
    const float4* __restrict__ x1 = x0 + (HH / 4);
    const float4* __restrict__ wr = (const float4*)ws;

    float a0 = 0.0f, a1 = 0.0f;
    #pragma unroll
    for (int j = 0; j < 8; ++j) {          // 256 float4 per row, 8 per lane
        const int idx = lane + 32 * j;
        const float4 w4 = wr[idx];
        const float4 v0 = x0[idx];
        const float4 v1 = x1[idx];
        a0 += v0.x * w4.x + v0.y * w4.y + v0.z * w4.z + v0.w * w4.w;
        a1 += v1.x * w4.x + v1.y * w4.y + v1.z * w4.z + v1.w * w4.w;
    }

    #pragma unroll
    for (int o = 16; o; o >>= 1) {
        a0 += __shfl_xor_sync(0xFFFFFFFFu, a0, o);
        a1 += __shfl_xor_sync(0xFFFFFFFFu, a1, o);
    }

    if (lane == 0) {
        const float bb = bias[0];
        g_h[r0]     = a0 + bb;
        g_h[r0 + 1] = a1 + bb;
    }
}

// ---------------------------------------------------------------------------
// Kernel 2: one block per batch row. Block-reduce masked min/max of h over the
// 4096 positions, then out = mask ? (h - hmin)/(hmax - hmin) : 0.
// g_h is L2-hot (just written), so this is a few microseconds.
// ---------------------------------------------------------------------------
__global__ __launch_bounds__(1024) void final_k(const int* __restrict__ mask,
                                                float* __restrict__ out)
{
    __shared__ float smin[32];
    __shared__ float smax[32];

    const int b = blockIdx.x;
    const int t = threadIdx.x;
    const int base = b << 12;                 // b * 4096

    float h[4];
    int   m[4];
    const float INF = __int_as_float(0x7f800000);
    float lmin = INF, lmax = -INF;

    #pragma unroll
    for (int i = 0; i < 4; ++i) {
        const int idx = base + (i << 10) + t; // coalesced
        h[i] = g_h[idx];
        m[i] = mask[idx];
        if (m[i]) { lmin = fminf(lmin, h[i]); lmax = fmaxf(lmax, h[i]); }
    }

    lmin = warp_min(lmin);
    lmax = warp_max(lmax);

    const int warp = t >> 5;
    const int lane = t & 31;
    if (lane == 0) { smin[warp] = lmin; smax[warp] = lmax; }
    __syncthreads();

    if (warp == 0) {
        float v0 = smin[lane];
        float v1 = smax[lane];
        v0 = warp_min(v0);
        v1 = warp_max(v1);
        if (lane == 0) { smin[0] = v0; smax[0] = v1; }
    }
    __syncthreads();

    const float hmin = smin[0];
    const float inv  = 1.0f / (smax[0] - hmin);

    #pragma unroll
    for (int i = 0; i < 4; ++i) {
        const int idx = base + (i << 10) + t;
        out[idx] = m[i] ? (h[i] - hmin) * inv : 0.0f;
    }
}

extern "C" void kernel_launch(void* const* d_in, const int* in_sizes, int n_in,
                              void* d_out, int out_size)
{
    const float* x    = (const float*)d_in[0];   // [B,S,H] fp32
    const int*   mask = (const int*)  d_in[1];   // [B,S]
    const float* W    = (const float*)d_in[2];   // [H]
    const float* bias = (const float*)d_in[3];   // [1]
    float*       out  = (float*)d_out;           // [B,S,1] fp32

    gemv_k<<<ROWS / 32, 512>>>(x, W, bias);
    final_k<<<BB, 1024>>>(mask, out);
}

// round 3
// speedup vs baseline: 1.4906x; 1.0055x over previous
#include <cuda_runtime.h>
#include <cuda_bf16.h>
#include <cstdint>

// Problem constants
#define BB 32
#define SS 4096
#define HH 1024
#define ROWS (BB * SS)   // 131072

// Scratch (device globals — zero-initialized at module load; replay-idempotent)
__device__ float        g_h[ROWS];
__device__ unsigned int g_maxenc[BB];  // max over enc(h)  of masked h
__device__ unsigned int g_negmin[BB];  // max over ~enc(h) of masked h  (== min)

// Order-preserving float -> uint encoding (monotonic under unsigned compare).
// enc(h) in (0, 0xFFFFFFFF) for all finite h, so 0 is a safe identity for max.
__device__ __forceinline__ unsigned int enc_f(float f) {
    unsigned int u = __float_as_uint(f);
    return (u & 0x80000000u) ? ~u : (u | 0x80000000u);
}
__device__ __forceinline__ float dec_f(unsigned int u) {
    u = (u & 0x80000000u) ? (u & 0x7FFFFFFFu) : ~u;
    return __uint_as_float(u);
}

// ---------------------------------------------------------------------------
// Kernel 1: h = x @ W + b, one warp per 2 rows, 512 threads/block.
// Each block covers 32 consecutive rows of ONE batch (4096 % 32 == 0); it also
// block-reduces the masked min/max of its 32 h values and RED-maxes them into
// the per-batch stats. Atomic traffic: 2 per block, hidden under the stream.
// ---------------------------------------------------------------------------
__global__ __launch_bounds__(512) void gemv_k(const float* __restrict__ x,
                                              const int*   __restrict__ mask,
                                              const float* __restrict__ W,
                                              const float* __restrict__ bias)
{
    __shared__ float        ws[HH];
    __shared__ unsigned int sMax[16];   // per-warp enc-max
    __shared__ unsigned int sNmn[16];   // per-warp ~enc-max

    const int tid = threadIdx.x;
    #pragma unroll
    for (int i = tid; i < HH; i += 512) ws[i] = W[i];
    __syncthreads();

    const int warp = tid >> 5;
    const int lane = tid & 31;
    const long long r0 = ((long long)blockIdx.x * 16 + warp) * 2;

    const float4* __restrict__ x0 = (const float4*)(x + r0 * HH);
    const float4* __restrict__ x1 = x0 + (HH / 4);
    const float4* __restrict__ wr = (const float4*)ws;

    float a0 = 0.0f, a1 = 0.0f;
    #pragma unroll
    for (int j = 0; j < 8; ++j) {          // 256 float4 per row, 8 per lane
        const int idx = lane + 32 * j;
        const float4 w4 = wr[idx];
        const float4 v0 = x0[idx];
        const float4 v1 = x1[idx];
        a0 += v0.x * w4.x + v0.y * w4.y + v0.z * w4.z + v0.w * w4.w;
        a1 += v1.x * w4.x + v1.y * w4.y + v1.z * w4.z + v1.w * w4.w;
    }

    #pragma unroll
    for (int o = 16; o; o >>= 1) {
        a0 += __shfl_xor_sync(0xFFFFFFFFu, a0, o);
        a1 += __shfl_xor_sync(0xFFFFFFFFu, a1, o);
    }

    if (lane == 0) {
        const float bb = bias[0];
        const float h0 = a0 + bb;
        const float h1 = a1 + bb;
        g_h[r0]     = h0;
        g_h[r0 + 1] = h1;

        const int m0 = mask[r0];
        const int m1 = mask[r0 + 1];
        const unsigned int e0 = enc_f(h0);
        const unsigned int e1 = enc_f(h1);
        unsigned int emax = 0u, enmn = 0u;
        if (m0) { emax = e0;               enmn = ~e0; }
        if (m1) { emax = max(emax, e1);    enmn = max(enmn, ~e1); }
        sMax[warp] = emax;
        sNmn[warp] = enmn;
    }
    __syncthreads();

    if (warp == 0) {
        unsigned int emax = (lane < 16) ? sMax[lane] : 0u;
        unsigned int enmn = (lane < 16) ? sNmn[lane] : 0u;
        #pragma unroll
        for (int o = 16; o; o >>= 1) {
            emax = max(emax, __shfl_xor_sync(0xFFFFFFFFu, emax, o));
            enmn = max(enmn, __shfl_xor_sync(0xFFFFFFFFu, enmn, o));
        }
        if (lane == 0) {
            const int b = (int)(r0 >> 12);
            atomicMax(&g_maxenc[b], emax);   // no return use -> REDG
            atomicMax(&g_negmin[b], enmn);
        }
    }
}

// ---------------------------------------------------------------------------
// Kernel 2: pure elementwise rescale. 512 blocks — fully parallel, L2-hot.
// ---------------------------------------------------------------------------
__global__ __launch_bounds__(256) void final_k(const int* __restrict__ mask,
                                               float* __restrict__ out)
{
    const int i = blockIdx.x * 256 + threadIdx.x;
    const int b = i >> 12;
    const float hmin = dec_f(~g_negmin[b]);
    const float hmax = dec_f(g_maxenc[b]);
    const float inv  = 1.0f / (hmax - hmin);
    const float h    = g_h[i];
    out[i] = mask[i] ? (h - hmin) * inv : 0.0f;
}

extern "C" void kernel_launch(void* const* d_in, const int* in_sizes, int n_in,
                              void* d_out, int out_size)
{
    const float* x    = (const float*)d_in[0];   // [B,S,H] fp32
    const int*   mask = (const int*)  d_in[1];   // [B,S]
    const float* W    = (const float*)d_in[2];   // [H]
    const float* bias = (const float*)d_in[3];   // [1]
    float*       out  = (float*)d_out;           // [B,S,1] fp32

    gemv_k<<<ROWS / 32, 512>>>(x, mask, W, bias);
    final_k<<<ROWS / 256, 256>>>(mask, out);
}